// round 1
// baseline (speedup 1.0000x reference)
#include <cuda_runtime.h>

#define NN   20000
#define EMB  128
#define HID  512     // 4*EMB
#define CN   1024    // 2*HID  (A part cols [0,512), B part cols [512,1024))

// -------- scratch (no allocations allowed) --------
__device__ float              g_C[(size_t)NN * CN];   // 82 MB node projections
__device__ float              g_Wp[EMB * CN];         // repacked [W1_top | W1_bot]
__device__ int                g_nmax[NN];             // ordered-int encoded segment max
__device__ unsigned long long g_nsum[NN];             // fixed-point segment sum (2^-42)

#define FIXSCALE 4398046511104.0   // 2^42

__device__ __forceinline__ int f2ord(float f) {
    int i = __float_as_int(f);
    return i >= 0 ? i : (i ^ 0x7FFFFFFF);
}
__device__ __forceinline__ float ord2f(int i) {
    return __int_as_float(i >= 0 ? i : (i ^ 0x7FFFFFFF));
}

// -------- kernel 0: init reduction buffers --------
__global__ void k_init() {
    int i = blockIdx.x * blockDim.x + threadIdx.x;
    if (i < NN) {
        g_nmax[i] = (int)0x80000000;  // INT_MIN < any encoded float
        g_nsum[i] = 0ull;
    }
}

// -------- kernel 1: repack W1[256,512] -> Wp[128,1024] --------
__global__ void k_repack(const float* __restrict__ W1) {
    int j = blockIdx.x * blockDim.x + threadIdx.x;
    if (j >= EMB * CN) return;
    int k = j >> 10;
    int n = j & (CN - 1);
    g_Wp[j] = (n < HID) ? W1[k * HID + n] : W1[(EMB + k) * HID + (n - HID)];
}

// -------- kernel 2: C[NN,1024] = h[NN,128] @ Wp (+b1 on A half) --------
// 64x64 tile, 256 threads, 4x4 per thread, BK=16
__global__ void k_gemm(const float* __restrict__ h, const float* __restrict__ b1) {
    __shared__ float As[16][64];
    __shared__ float Bs[16][64];
    const int bm = blockIdx.y * 64;
    const int bn = blockIdx.x * 64;
    const int tid = threadIdx.x;

    const int a_row = tid >> 2;            // 0..63
    const int a_col = (tid & 3) << 2;      // 0,4,8,12
    const int b_row = tid >> 4;            // 0..15
    const int b_col = (tid & 15) << 2;     // 0..60
    const int tm = (tid >> 4) << 2;        // 0..60
    const int tn = (tid & 15) << 2;        // 0..60

    float acc[4][4] = {};

    for (int k0 = 0; k0 < EMB; k0 += 16) {
        int gm = bm + a_row;
        float4 av = (gm < NN) ? *(const float4*)(h + (size_t)gm * EMB + k0 + a_col)
                              : make_float4(0.f, 0.f, 0.f, 0.f);
        As[a_col + 0][a_row] = av.x;
        As[a_col + 1][a_row] = av.y;
        As[a_col + 2][a_row] = av.z;
        As[a_col + 3][a_row] = av.w;
        *(float4*)&Bs[b_row][b_col] =
            *(const float4*)(g_Wp + (size_t)(k0 + b_row) * CN + bn + b_col);
        __syncthreads();

#pragma unroll
        for (int k = 0; k < 16; k++) {
            float4 a = *(float4*)&As[k][tm];
            float4 b = *(float4*)&Bs[k][tn];
            float ar[4] = {a.x, a.y, a.z, a.w};
            float br[4] = {b.x, b.y, b.z, b.w};
#pragma unroll
            for (int i = 0; i < 4; i++)
#pragma unroll
                for (int j = 0; j < 4; j++)
                    acc[i][j] = fmaf(ar[i], br[j], acc[i][j]);
        }
        __syncthreads();
    }

    const int n = bn + tn;
    float4 bias = (n < HID) ? *(const float4*)(b1 + n) : make_float4(0.f, 0.f, 0.f, 0.f);
#pragma unroll
    for (int i = 0; i < 4; i++) {
        int gm = bm + tm + i;
        if (gm >= NN) continue;
        float4 o = make_float4(acc[i][0] + bias.x, acc[i][1] + bias.y,
                               acc[i][2] + bias.z, acc[i][3] + bias.w);
        *(float4*)(g_C + (size_t)gm * CN + n) = o;
    }
}

// -------- kernel 3: warp per edge: score + segment max --------
__global__ void k_edge(const int* __restrict__ row, const int* __restrict__ col,
                       const float* __restrict__ W2, const float* __restrict__ b2,
                       float* __restrict__ scores_out, int E) {
    int gt = blockIdx.x * blockDim.x + threadIdx.x;
    int e = gt >> 5;
    int lane = gt & 31;
    if (e >= E) return;

    int r = row[e], c = col[e];
    const float4* pa = (const float4*)(g_C + (size_t)r * CN);         // A: cols 0..511
    const float4* pb = (const float4*)(g_C + (size_t)c * CN + HID);   // B: cols 512..1023
    const float4* pw = (const float4*)W2;

    float acc = 0.f;
#pragma unroll
    for (int i = 0; i < 4; i++) {
        float4 a = pa[lane + i * 32];
        float4 b = pb[lane + i * 32];
        float4 w = __ldg(&pw[lane + i * 32]);
        acc = fmaf(fmaxf(a.x + b.x, 0.f), w.x, acc);
        acc = fmaf(fmaxf(a.y + b.y, 0.f), w.y, acc);
        acc = fmaf(fmaxf(a.z + b.z, 0.f), w.z, acc);
        acc = fmaf(fmaxf(a.w + b.w, 0.f), w.w, acc);
    }
#pragma unroll
    for (int o = 16; o; o >>= 1) acc += __shfl_xor_sync(0xFFFFFFFFu, acc, o);

    if (lane == 0) {
        float s = acc + b2[0];
        scores_out[e] = s;
        atomicMax(&g_nmax[r], f2ord(s));
    }
}

// -------- kernel 4: deterministic fixed-point segment sum --------
__global__ void k_sum(const float* __restrict__ scores, const int* __restrict__ row, int E) {
    int e = blockIdx.x * blockDim.x + threadIdx.x;
    if (e >= E) return;
    int r = row[e];
    float m = ord2f(g_nmax[r]);
    float ex = expf(scores[e] - m);                         // <= 1
    unsigned long long q = (unsigned long long)((double)ex * FIXSCALE);
    atomicAdd(&g_nsum[r], q);
}

// -------- kernel 5: probs -> logits -> relaxed bernoulli -> outputs --------
__global__ void k_final(const float* __restrict__ scores, const int* __restrict__ row,
                        const float* __restrict__ u, const int* __restrict__ edge_mask,
                        const int* __restrict__ hier, float* __restrict__ out, int E) {
    int e = blockIdx.x * blockDim.x + threadIdx.x;
    if (e >= E) return;
    int r = row[e];
    float s = scores[e];
    float m = ord2f(g_nmax[r]);
    float ex = expf(s - m);
    float ssum = (float)((double)g_nsum[r] * (1.0 / FIXSCALE));
    float p = fminf(ex / ssum, 1.0f);

    float logits = logf(p) - log1pf(-p);
    float uu = u[e];
    float x = logits + (logf(uu) - log1pf(-uu));
    float y = 1.0f / (1.0f + expf(-x));
    bool hard = (y > 0.5f);                                 // y_st forward == y_hard exactly

    int nm = hard ? (hier[0] + 1) : edge_mask[e];
    out[(size_t)E + e]     = hard ? 1.0f : 0.0f;            // y_st
    out[(size_t)2 * E + e] = (float)nm;                     // new_mask
    out[(size_t)3 * E + e] = (nm > 0) ? s : 0.0f;           // causal_w
    out[(size_t)4 * E + e] = (nm == -1) ? -s : 0.0f;        // spu_w
}

extern "C" void kernel_launch(void* const* d_in, const int* in_sizes, int n_in,
                              void* d_out, int out_size) {
    const float* h     = (const float*)d_in[0];
    const float* W1    = (const float*)d_in[1];
    const float* b1    = (const float*)d_in[2];
    const float* W2    = (const float*)d_in[3];
    const float* b2    = (const float*)d_in[4];
    const float* u     = (const float*)d_in[5];
    const int*   row   = (const int*)d_in[6];
    const int*   col   = (const int*)d_in[7];
    const int*   emask = (const int*)d_in[8];
    const int*   hier  = (const int*)d_in[9];
    float* out = (float*)d_out;
    int E = in_sizes[5];

    k_init<<<(NN + 255) / 256, 256>>>();
    k_repack<<<(EMB * CN + 255) / 256, 256>>>(W1);
    dim3 gg(CN / 64, (NN + 63) / 64);
    k_gemm<<<gg, 256>>>(h, b1);
    k_edge<<<(E * 32 + 255) / 256, 256>>>(row, col, W2, b2, out, E);
    k_sum<<<(E + 255) / 256, 256>>>(out, row, E);
    k_final<<<(E + 255) / 256, 256>>>(out, row, u, emask, hier, out, E);
}

// round 2
// speedup vs baseline: 1.0526x; 1.0526x over previous
#include <cuda_runtime.h>

#define NN   20000
#define EMB  128
#define HID  512     // 4*EMB
#define CN   1024    // 2*HID  (A part cols [0,512), B part cols [512,1024))

// -------- scratch (no allocations allowed) --------
__device__ float              g_C[(size_t)NN * CN];   // 82 MB node projections
__device__ float              g_Wp[EMB * CN];         // repacked [W1_top | W1_bot], layout [k][n]
__device__ int                g_nmax[NN];             // ordered-int encoded segment max
__device__ unsigned long long g_nsum[NN];             // fixed-point segment sum (2^-42)

#define FIXSCALE 4398046511104.0   // 2^42

__device__ __forceinline__ int f2ord(float f) {
    int i = __float_as_int(f);
    return i >= 0 ? i : (i ^ 0x7FFFFFFF);
}
__device__ __forceinline__ float ord2f(int i) {
    return __int_as_float(i >= 0 ? i : (i ^ 0x7FFFFFFF));
}

// -------- packed fp32x2 helpers (sm_103a FFMA2) --------
__device__ __forceinline__ unsigned long long pk2(float lo, float hi) {
    unsigned long long r;
    asm("mov.b64 %0, {%1, %2};" : "=l"(r) : "f"(lo), "f"(hi));
    return r;
}
__device__ __forceinline__ unsigned long long ffma2(unsigned long long a,
                                                    unsigned long long b,
                                                    unsigned long long c) {
    unsigned long long d;
    asm("fma.rn.f32x2 %0, %1, %2, %3;" : "=l"(d) : "l"(a), "l"(b), "l"(c));
    return d;
}
__device__ __forceinline__ float2 upk2(unsigned long long v) {
    float2 f;
    asm("mov.b64 {%0, %1}, %2;" : "=f"(f.x), "=f"(f.y) : "l"(v));
    return f;
}

// -------- kernel 0: init reduction buffers --------
__global__ void k_init() {
    int i = blockIdx.x * blockDim.x + threadIdx.x;
    if (i < NN) {
        g_nmax[i] = (int)0x80000000;
        g_nsum[i] = 0ull;
    }
}

// -------- kernel 1: repack W1[256,512] -> Wp[128,1024] (layout [k][n]) --------
__global__ void k_repack(const float* __restrict__ W1) {
    int j = blockIdx.x * blockDim.x + threadIdx.x;
    if (j >= EMB * CN) return;
    int k = j >> 10;
    int n = j & (CN - 1);
    g_Wp[j] = (n < HID) ? W1[k * HID + n] : W1[(EMB + k) * HID + (n - HID)];
}

// -------- kernel 2: C[NN,1024] = h[NN,128] @ Wp (+b1 on A half) --------
// 128x64 tile, 256 threads, BK=32, 8x4 per thread via packed FFMA2.
#define BM 128
#define BN 64
#define BK 32

__global__ void __launch_bounds__(256) k_gemm(const float* __restrict__ h,
                                              const float* __restrict__ b1) {
    __shared__ unsigned long long As2[BK][BM + 1];  // {a,a} duplicated pairs, 33 KB
    __shared__ float Bs[BK][BN];                    // 8 KB

    const int bm = blockIdx.y * BM;
    const int bn = blockIdx.x * BN;
    const int t  = threadIdx.x;
    const int tx = t & 15;   // n group: 4 cols
    const int ty = t >> 4;   // m group: 8 rows
    const int n  = bn + tx * 4;

    unsigned long long acc[8][2] = {};  // bit pattern 0 == {0.f,0.f}

    for (int k0 = 0; k0 < EMB; k0 += BK) {
        // stage A: BM*BK floats = 1024 float4; thread handles f = t + q*256
        // f -> m = f>>3, kc = (f&7)*4   (8 float4 per 32-wide k row)
#pragma unroll
        for (int q = 0; q < 4; q++) {
            int f  = t + q * 256;
            int m  = f >> 3;
            int kc = (f & 7) << 2;
            int gm = bm + m;
            float4 v = (gm < NN)
                ? *(const float4*)(h + (size_t)gm * EMB + k0 + kc)
                : make_float4(0.f, 0.f, 0.f, 0.f);
            As2[kc + 0][m] = pk2(v.x, v.x);
            As2[kc + 1][m] = pk2(v.y, v.y);
            As2[kc + 2][m] = pk2(v.z, v.z);
            As2[kc + 3][m] = pk2(v.w, v.w);
        }
        // stage B: BK*BN floats = 512 float4; f = t + q*256 -> k = f>>4, nc=(f&15)*4
#pragma unroll
        for (int q = 0; q < 2; q++) {
            int f  = t + q * 256;
            int kk = f >> 4;
            int nc = (f & 15) << 2;
            *(float4*)&Bs[kk][nc] =
                *(const float4*)(g_Wp + (size_t)(k0 + kk) * CN + bn + nc);
        }
        __syncthreads();

#pragma unroll
        for (int k = 0; k < BK; k++) {
            float4 b = *(float4*)&Bs[k][tx * 4];
            unsigned long long b01 = pk2(b.x, b.y);
            unsigned long long b23 = pk2(b.z, b.w);
#pragma unroll
            for (int i = 0; i < 8; i++) {
                unsigned long long aa = As2[k][ty * 8 + i];
                acc[i][0] = ffma2(aa, b01, acc[i][0]);
                acc[i][1] = ffma2(aa, b23, acc[i][1]);
            }
        }
        __syncthreads();
    }

    float4 bias = (n < HID) ? *(const float4*)(b1 + n)
                            : make_float4(0.f, 0.f, 0.f, 0.f);
#pragma unroll
    for (int i = 0; i < 8; i++) {
        int gm = bm + ty * 8 + i;
        if (gm >= NN) continue;
        float2 lo = upk2(acc[i][0]);
        float2 hi = upk2(acc[i][1]);
        float4 o = make_float4(lo.x + bias.x, lo.y + bias.y,
                               hi.x + bias.z, hi.y + bias.w);
        *(float4*)(g_C + (size_t)gm * CN + n) = o;
    }
}

// -------- kernel 3: 16 lanes per edge (2 edges/warp): score + segment max --------
__global__ void __launch_bounds__(256) k_edge(const int* __restrict__ row,
                                              const int* __restrict__ col,
                                              const float* __restrict__ W2,
                                              const float* __restrict__ b2,
                                              float* __restrict__ scores_out, int E) {
    int gt   = blockIdx.x * blockDim.x + threadIdx.x;
    int warp = gt >> 5;
    int lane = gt & 31;
    int e    = warp * 2 + (lane >> 4);
    int sub  = lane & 15;
    if (e >= E) return;

    int r = row[e], c = col[e];
    const float4* pa = (const float4*)(g_C + (size_t)r * CN);         // cols 0..511
    const float4* pb = (const float4*)(g_C + (size_t)c * CN + HID);   // cols 512..1023
    const float4* pw = (const float4*)W2;

    float acc = 0.f;
#pragma unroll
    for (int i = 0; i < 8; i++) {
        int idx = sub + i * 16;
        float4 a = pa[idx];
        float4 b = pb[idx];
        float4 w = __ldg(&pw[idx]);
        acc = fmaf(fmaxf(a.x + b.x, 0.f), w.x, acc);
        acc = fmaf(fmaxf(a.y + b.y, 0.f), w.y, acc);
        acc = fmaf(fmaxf(a.z + b.z, 0.f), w.z, acc);
        acc = fmaf(fmaxf(a.w + b.w, 0.f), w.w, acc);
    }
#pragma unroll
    for (int o = 8; o; o >>= 1) acc += __shfl_xor_sync(0xFFFFFFFFu, acc, o);

    if (sub == 0) {
        float s = acc + b2[0];
        scores_out[e] = s;
        atomicMax(&g_nmax[r], f2ord(s));
    }
}

// -------- kernel 4: deterministic fixed-point segment sum --------
__global__ void k_sum(const float* __restrict__ scores, const int* __restrict__ row, int E) {
    int e = blockIdx.x * blockDim.x + threadIdx.x;
    if (e >= E) return;
    int r = row[e];
    float m = ord2f(g_nmax[r]);
    float ex = expf(scores[e] - m);                         // <= 1
    unsigned long long q = (unsigned long long)((double)ex * FIXSCALE);
    atomicAdd(&g_nsum[r], q);
}

// -------- kernel 5: probs -> logits -> relaxed bernoulli -> outputs --------
__global__ void k_final(const float* __restrict__ scores, const int* __restrict__ row,
                        const float* __restrict__ u, const int* __restrict__ edge_mask,
                        const int* __restrict__ hier, float* __restrict__ out, int E) {
    int e = blockIdx.x * blockDim.x + threadIdx.x;
    if (e >= E) return;
    int r = row[e];
    float s = scores[e];
    float m = ord2f(g_nmax[r]);
    float ex = expf(s - m);
    float ssum = (float)((double)g_nsum[r] * (1.0 / FIXSCALE));
    float p = fminf(ex / ssum, 1.0f);

    float logits = logf(p) - log1pf(-p);
    float uu = u[e];
    float x = logits + (logf(uu) - log1pf(-uu));
    float y = 1.0f / (1.0f + expf(-x));
    bool hard = (y > 0.5f);                                 // y_st forward == y_hard exactly

    int nm = hard ? (hier[0] + 1) : edge_mask[e];
    out[(size_t)E + e]     = hard ? 1.0f : 0.0f;            // y_st
    out[(size_t)2 * E + e] = (float)nm;                     // new_mask
    out[(size_t)3 * E + e] = (nm > 0) ? s : 0.0f;           // causal_w
    out[(size_t)4 * E + e] = (nm == -1) ? -s : 0.0f;        // spu_w
}

extern "C" void kernel_launch(void* const* d_in, const int* in_sizes, int n_in,
                              void* d_out, int out_size) {
    const float* h     = (const float*)d_in[0];
    const float* W1    = (const float*)d_in[1];
    const float* b1    = (const float*)d_in[2];
    const float* W2    = (const float*)d_in[3];
    const float* b2    = (const float*)d_in[4];
    const float* u     = (const float*)d_in[5];
    const int*   row   = (const int*)d_in[6];
    const int*   col   = (const int*)d_in[7];
    const int*   emask = (const int*)d_in[8];
    const int*   hier  = (const int*)d_in[9];
    float* out = (float*)d_out;
    int E = in_sizes[5];

    k_init<<<(NN + 255) / 256, 256>>>();
    k_repack<<<(EMB * CN + 255) / 256, 256>>>(W1);
    dim3 gg(CN / BN, (NN + BM - 1) / BM);
    k_gemm<<<gg, 256>>>(h, b1);
    k_edge<<<(E * 16 + 255) / 256, 256>>>(row, col, W2, b2, out, E);
    k_sum<<<(E + 255) / 256, 256>>>(out, row, E);
    k_final<<<(E + 255) / 256, 256>>>(out, row, u, emask, hier, out, E);
}